// round 17
// baseline (speedup 1.0000x reference)
#include <cuda_runtime.h>
#include <cuda_bf16.h>
#include <cstdint>
#include <math.h>

#define B_   8
#define T_   1024
#define C_   2048
#define H_   16
#define HKV_ 4
#define HD_  128
#define CKV_ 512
#define MTOT (B_ * T_)      // 8192
#define NQKV 3072           // 2048 | 512 | 512

// Scratch (device globals: allocation-free per harness rules)
__device__ __nv_bfloat16 g_xhi[(size_t)MTOT * C_];
__device__ __nv_bfloat16 g_xlo[(size_t)MTOT * C_];
__device__ __nv_bfloat16 g_yhi[(size_t)MTOT * C_];
__device__ __nv_bfloat16 g_ylo[(size_t)MTOT * C_];
__device__ __nv_bfloat16 g_qhi[(size_t)MTOT * C_];
__device__ __nv_bfloat16 g_qlo[(size_t)MTOT * C_];
__device__ __nv_bfloat16 g_khi[(size_t)MTOT * CKV_];
__device__ __nv_bfloat16 g_klo[(size_t)MTOT * CKV_];
__device__ __nv_bfloat16 g_vhi[(size_t)MTOT * CKV_];
__device__ __nv_bfloat16 g_vlo[(size_t)MTOT * CKV_];
__device__ __nv_bfloat16 g_whi[(size_t)C_ * NQKV];
__device__ __nv_bfloat16 g_wlo[(size_t)C_ * NQKV];
__device__ __nv_bfloat16 g_wohi[(size_t)C_ * C_];
__device__ __nv_bfloat16 g_wolo[(size_t)C_ * C_];

__device__ __forceinline__ void cpa16(uint32_t saddr, const void* g) {
    asm volatile("cp.async.cg.shared.global [%0], [%1], 16;\n"
                 :: "r"(saddr), "l"(g));
}

// ---------------------------------------------------------------------------
// mma.sync / ldmatrix helpers (sm_80 baseline — safe on plain sm_103 target)
// ---------------------------------------------------------------------------
__device__ __forceinline__ void ldsm4(uint32_t* r, uint32_t a) {
    asm volatile("ldmatrix.sync.aligned.m8n8.x4.shared.b16 {%0,%1,%2,%3}, [%4];"
                 : "=r"(r[0]), "=r"(r[1]), "=r"(r[2]), "=r"(r[3]) : "r"(a));
}
__device__ __forceinline__ void ldsm4t(uint32_t* r, uint32_t a) {
    asm volatile("ldmatrix.sync.aligned.m8n8.x4.trans.shared.b16 {%0,%1,%2,%3}, [%4];"
                 : "=r"(r[0]), "=r"(r[1]), "=r"(r[2]), "=r"(r[3]) : "r"(a));
}
__device__ __forceinline__ void mma_bf(float* d, const uint32_t* a,
                                       uint32_t b0, uint32_t b1) {
    asm volatile("mma.sync.aligned.m16n8k16.row.col.f32.bf16.bf16.f32 "
                 "{%0,%1,%2,%3}, {%4,%5,%6,%7}, {%8,%9}, {%0,%1,%2,%3};"
                 : "+f"(d[0]), "+f"(d[1]), "+f"(d[2]), "+f"(d[3])
                 : "r"(a[0]), "r"(a[1]), "r"(a[2]), "r"(a[3]), "r"(b0), "r"(b1));
}
__device__ __forceinline__ uint32_t packsplit(float a, float b, uint32_t* lo) {
    __nv_bfloat162 h = __floats2bfloat162_rn(a, b);
    float ra = a - __bfloat162float(h.x);
    float rb = b - __bfloat162float(h.y);
    __nv_bfloat162 l = __floats2bfloat162_rn(ra, rb);
    *lo = *(uint32_t*)&l;
    return *(uint32_t*)&h;
}

// ---------------------------------------------------------------------------
// fp32 -> bf16 (hi, lo) split, vectorized x4
// ---------------------------------------------------------------------------
union BF4 { __nv_bfloat16 b[4]; uint2 u; };

__device__ __forceinline__ void split4(float4 v, __nv_bfloat16* hi,
                                       __nv_bfloat16* lo, size_t i) {
    float f[4] = {v.x, v.y, v.z, v.w};
    BF4 h, l;
#pragma unroll
    for (int j = 0; j < 4; j++) {
        h.b[j] = __float2bfloat16_rn(f[j]);
        l.b[j] = __float2bfloat16_rn(f[j] - __bfloat162float(h.b[j]));
    }
    *(uint2*)(hi + i) = h.u;
    *(uint2*)(lo + i) = l.u;
}

__global__ void split_kernel(const float* __restrict__ in,
                             __nv_bfloat16* __restrict__ hi,
                             __nv_bfloat16* __restrict__ lo, int n)
{
    size_t i = ((size_t)blockIdx.x * blockDim.x + threadIdx.x) * 4;
    if (i >= (size_t)n) return;
    split4(*(const float4*)(in + i), hi, lo, i);
}

__global__ void packw_kernel(const float* __restrict__ wq,
                             const float* __restrict__ wk,
                             const float* __restrict__ wv,
                             __nv_bfloat16* __restrict__ hi,
                             __nv_bfloat16* __restrict__ lo)
{
    size_t i = ((size_t)blockIdx.x * blockDim.x + threadIdx.x) * 4;
    if (i >= (size_t)C_ * NQKV) return;
    int r = (int)(i / NQKV), j = (int)(i % NQKV);
    const float* src;
    if (j < 2048)      src = wq + (size_t)r * 2048 + j;
    else if (j < 2560) src = wk + (size_t)r * 512 + (j - 2048);
    else               src = wv + (size_t)r * 512 + (j - 2560);
    split4(*(const float4*)src, hi, lo, i);
}

// ---------------------------------------------------------------------------
// Pure-bf16 tensor-core GEMM, raw mma.sync, 4 warps/CTA, 64x64 warp tile,
// 2-stage cp.async, 2 CTAs/SM (proven 68% tensor config).
// qkvMode=1: epilogue routes segments — q (rope+scale+split), k (rope+split),
// v (split) — RoPE fused here because BN=128 tiles are head-aligned, so each
// tile holds complete (i, i+64) rotation pairs. Deletes the standalone
// rope_split kernels and the fp32 q/k round trip.
// qkvMode=0: plain fp32 store to dOut (out projection).
// ---------------------------------------------------------------------------
#define BM 128
#define BN 128
#define BK 32
#define PA 40
#define PB 136
#define ASZ (BM * PA)
#define BSZ (BK * PB)
#define G2_SMEM ((4 * ASZ + 4 * BSZ) * 2)   // 75776 B (>= 128*130*4 = 66560)

__global__ __launch_bounds__(128, 2) void hgemm2(
    const __nv_bfloat16* __restrict__ Ahi, const __nv_bfloat16* __restrict__ Alo,
    const __nv_bfloat16* __restrict__ Bhi, const __nv_bfloat16* __restrict__ Blo,
    int N, int K, float* dOut, int qkvMode,
    const float* __restrict__ sp, const float* __restrict__ cp)
{
    extern __shared__ __nv_bfloat16 smemg[];
    const uint32_t sAb = (uint32_t)__cvta_generic_to_shared(smemg);
    const uint32_t sBb = sAb + 4 * ASZ * 2;

    const int tid  = threadIdx.x;
    const int w    = tid >> 5;
    const int lane = tid & 31;
    const int warpM = w & 1;
    const int warpN = w >> 1;
    const int m0 = blockIdx.y * BM;
    const int n0 = blockIdx.x * BN;
    const int NCH = K / BK;

    float acc[4][8][4];
#pragma unroll
    for (int mt = 0; mt < 4; mt++)
#pragma unroll
        for (int n8 = 0; n8 < 8; n8++)
#pragma unroll
            for (int e = 0; e < 4; e++) acc[mt][n8][e] = 0.f;

#define LOADC(CH, STG) do {                                                   \
        const int k0_ = (CH) * BK;                                            \
        _Pragma("unroll")                                                     \
        for (int it = 0; it < 4; it++) {                                      \
            int v = it * 128 + tid;                                           \
            int ar = v >> 2, ac = (v & 3) * 8;                                \
            size_t ag = (size_t)(m0 + ar) * K + k0_ + ac;                     \
            uint32_t as = (uint32_t)(ar * PA + ac) * 2;                       \
            cpa16(sAb + ((STG) * ASZ) * 2 + as, Ahi + ag);                    \
            cpa16(sAb + ((2 + (STG)) * ASZ) * 2 + as, Alo + ag);              \
            int br = v >> 4, bc = (v & 15) * 8;                               \
            size_t bg = (size_t)(k0_ + br) * N + n0 + bc;                     \
            uint32_t bs = (uint32_t)(br * PB + bc) * 2;                       \
            cpa16(sBb + ((STG) * BSZ) * 2 + bs, Bhi + bg);                    \
            cpa16(sBb + ((2 + (STG)) * BSZ) * 2 + bs, Blo + bg);              \
        }                                                                     \
        asm volatile("cp.async.commit_group;" ::: "memory");                  \
    } while (0)

    LOADC(0, 0);
    LOADC(1, 1);

    for (int c = 0; c < NCH; c++) {
        const int st = c & 1;
        if (c + 1 < NCH) asm volatile("cp.async.wait_group 1;" ::: "memory");
        else             asm volatile("cp.async.wait_group 0;" ::: "memory");
        __syncthreads();

        const uint32_t aH = sAb + (st * ASZ) * 2;
        const uint32_t aL = sAb + ((2 + st) * ASZ) * 2;
        const uint32_t bH = sBb + (st * BSZ) * 2;
        const uint32_t bL = sBb + ((2 + st) * BSZ) * 2;

#pragma unroll
        for (int ks = 0; ks < 2; ks++) {
            uint32_t bh[4][4], bl[4][4];
#pragma unroll
            for (int n16 = 0; n16 < 4; n16++) {
                uint32_t baddr = bH +
                    (((uint32_t)(ks * 16 + (lane & 15))) * PB +
                     (uint32_t)(warpN * 64 + n16 * 16 + (lane >> 4) * 8)) * 2;
                ldsm4t(bh[n16], baddr);
                ldsm4t(bl[n16], baddr + (bL - bH));
            }
#pragma unroll
            for (int mt = 0; mt < 4; mt++) {
                uint32_t aaddr = aH +
                    (((uint32_t)(warpM * 64 + mt * 16 + (lane & 15))) * PA +
                     (uint32_t)(ks * 16 + (lane >> 4) * 8)) * 2;
                uint32_t ah[4], al[4];
                ldsm4(ah, aaddr);
                ldsm4(al, aaddr + (aL - aH));
#pragma unroll
                for (int n16 = 0; n16 < 4; n16++) {
                    mma_bf(acc[mt][2 * n16],     ah, bh[n16][0], bh[n16][1]);
                    mma_bf(acc[mt][2 * n16 + 1], ah, bh[n16][2], bh[n16][3]);
                }
#pragma unroll
                for (int n16 = 0; n16 < 4; n16++) {
                    mma_bf(acc[mt][2 * n16],     ah, bl[n16][0], bl[n16][1]);
                    mma_bf(acc[mt][2 * n16 + 1], ah, bl[n16][2], bl[n16][3]);
                }
#pragma unroll
                for (int n16 = 0; n16 < 4; n16++) {
                    mma_bf(acc[mt][2 * n16],     al, bh[n16][0], bh[n16][1]);
                    mma_bf(acc[mt][2 * n16 + 1], al, bh[n16][2], bh[n16][3]);
                }
            }
        }
        __syncthreads();
        if (c + 2 < NCH) LOADC(c + 2, st);
    }

    if (!qkvMode) {
        // Out projection: plain fp32 store
#pragma unroll
        for (int mt = 0; mt < 4; mt++) {
            int r = m0 + warpM * 64 + mt * 16 + (lane >> 2);
#pragma unroll
            for (int n8 = 0; n8 < 8; n8++) {
                float* cp0 = dOut + (size_t)r * N + n0 + warpN * 64 + n8 * 8 + (lane & 3) * 2;
                *(float2*)cp0           = make_float2(acc[mt][n8][0], acc[mt][n8][1]);
                *(float2*)(cp0 + 8 * N) = make_float2(acc[mt][n8][2], acc[mt][n8][3]);
            }
        }
        return;
    }

    if (n0 >= 2560) {
        // V segment: direct packsplit (no rope)
        int nc = n0 - 2560;
#pragma unroll
        for (int mt = 0; mt < 4; mt++) {
            int r = m0 + warpM * 64 + mt * 16 + (lane >> 2);
#pragma unroll
            for (int n8 = 0; n8 < 8; n8++) {
                size_t off = (size_t)r * CKV_ + nc + warpN * 64 + n8 * 8 + (lane & 3) * 2;
                uint32_t lo0, lo1;
                uint32_t hi0 = packsplit(acc[mt][n8][0], acc[mt][n8][1], &lo0);
                uint32_t hi1 = packsplit(acc[mt][n8][2], acc[mt][n8][3], &lo1);
                *(uint32_t*)(g_vhi + off)            = hi0;
                *(uint32_t*)(g_vlo + off)            = lo0;
                *(uint32_t*)(g_vhi + off + 8 * CKV_) = hi1;
                *(uint32_t*)(g_vlo + off + 8 * CKV_) = lo1;
            }
        }
        return;
    }

    // Q / K segments: stage acc through smem, apply RoPE + split.
    // (Safe to overwrite smem: final loop iteration ended with __syncthreads.)
    float* sE = (float*)smemg;   // [128][130] fp32
#pragma unroll
    for (int mt = 0; mt < 4; mt++) {
        int r = warpM * 64 + mt * 16 + (lane >> 2);
#pragma unroll
        for (int n8 = 0; n8 < 8; n8++) {
            int col = warpN * 64 + n8 * 8 + (lane & 3) * 2;
            *(float2*)&sE[r * 130 + col]       = make_float2(acc[mt][n8][0], acc[mt][n8][1]);
            *(float2*)&sE[(r + 8) * 130 + col] = make_float2(acc[mt][n8][2], acc[mt][n8][3]);
        }
    }
    __syncthreads();

    const bool isQ = (n0 < 2048);
    const float scl = isQ ? 0.08838834764831845f : 1.0f;
    __nv_bfloat16* dh = isQ ? g_qhi : g_khi;
    __nv_bfloat16* dl = isQ ? g_qlo : g_klo;
    const int wd = isQ ? C_ : CKV_;
    const int nc = isQ ? n0 : (n0 - 2048);

    {
        int r = tid;                       // one row per thread
        int grow = m0 + r;
        int t = grow & (T_ - 1);
        const float* spr = sp + t * HD_;
        const float* cpr = cp + t * HD_;
        size_t drow = (size_t)grow * wd + nc;
        const float* row = &sE[r * 130];
#pragma unroll 8
        for (int c2 = 0; c2 < 64; c2 += 2) {
            float a0 = row[c2],      a1 = row[c2 + 1];
            float b0 = row[c2 + 64], b1 = row[c2 + 65];
            float s0 = spr[c2], s1 = spr[c2 + 1];
            float s2 = spr[c2 + 64], s3 = spr[c2 + 65];
            float cc0 = cpr[c2], cc1 = cpr[c2 + 1];
            float cc2 = cpr[c2 + 64], cc3 = cpr[c2 + 65];
            float o0 = (a0 * cc0 - b0 * s0) * scl;
            float o1 = (a1 * cc1 - b1 * s1) * scl;
            float o2 = (b0 * cc2 + a0 * s2) * scl;
            float o3 = (b1 * cc3 + a1 * s3) * scl;
            uint32_t lo0, lo1;
            uint32_t hi0 = packsplit(o0, o1, &lo0);
            uint32_t hi1 = packsplit(o2, o3, &lo1);
            *(uint32_t*)(dh + drow + c2)      = hi0;
            *(uint32_t*)(dl + drow + c2)      = lo0;
            *(uint32_t*)(dh + drow + c2 + 64) = hi1;
            *(uint32_t*)(dl + drow + c2 + 64) = lo1;
        }
    }
#undef LOADC
}

// ---------------------------------------------------------------------------
// attn4: FA2-style tensor-core flash attention (causal, no online max).
// 256 threads / 8 warps, CTA = 128 q-rows. cp.async double-buffered KV,
// one barrier per tile, per-warp early-out on masked tiles.
// ---------------------------------------------------------------------------
#define KSTR 136
#define TILE64B (64 * KSTR * 2)
#define OQ4HI 0
#define OQ4LO (128 * KSTR * 2)
#define OSTG  (2 * 128 * KSTR * 2)
#define STGSZ (4 * TILE64B)
#define ATTN4_SMEM (OSTG + 2 * STGSZ)

__global__ __launch_bounds__(256) void attn4()
{
    extern __shared__ char sm4[];
    const uint32_t sb = (uint32_t)__cvta_generic_to_shared(sm4);
    __nv_bfloat16* sQhi = (__nv_bfloat16*)(sm4 + OQ4HI);
    __nv_bfloat16* sQlo = (__nv_bfloat16*)(sm4 + OQ4LO);

    const int qt   = blockIdx.x;
    const int h    = blockIdx.y;
    const int b    = blockIdx.z;
    const int q0   = qt * 128;
    const int kvh  = h & 3;
    const int tid  = threadIdx.x;
    const int w    = tid >> 5;
    const int lane = tid & 31;

    {
        const __nv_bfloat16* gq_h = g_qhi + ((size_t)(b * T_ + q0)) * C_ + h * HD_;
        const __nv_bfloat16* gq_l = g_qlo + ((size_t)(b * T_ + q0)) * C_ + h * HD_;
#pragma unroll
        for (int it = 0; it < 8; it++) {
            int v = it * 256 + tid;
            int r = v >> 4, c = (v & 15) * 8;
            *(uint4*)(sQhi + r * KSTR + c) = *(const uint4*)(gq_h + (size_t)r * C_ + c);
            *(uint4*)(sQlo + r * KSTR + c) = *(const uint4*)(gq_l + (size_t)r * C_ + c);
        }
    }
    __syncthreads();

    uint32_t qh[8][4], ql[8][4];
#pragma unroll
    for (int kc = 0; kc < 8; kc++) {
        uint32_t row = (uint32_t)(w * 16 + (lane & 15));
        uint32_t col = (uint32_t)(kc * 16 + (lane >> 4) * 8);
        uint32_t a = sb + OQ4HI + (row * KSTR + col) * 2;
        ldsm4(qh[kc], a);
        ldsm4(ql[kc], a + (OQ4LO - OQ4HI));
    }

    float o[16][4];
#pragma unroll
    for (int i = 0; i < 16; i++)
#pragma unroll
        for (int j = 0; j < 4; j++) o[i][j] = 0.f;
    float l0 = 0.f, l1 = 0.f;

    const __nv_bfloat16* gk_h = g_khi + (size_t)b * T_ * CKV_ + kvh * HD_;
    const __nv_bfloat16* gk_l = g_klo + (size_t)b * T_ * CKV_ + kvh * HD_;
    const __nv_bfloat16* gv_h = g_vhi + (size_t)b * T_ * CKV_ + kvh * HD_;
    const __nv_bfloat16* gv_l = g_vlo + (size_t)b * T_ * CKV_ + kvh * HD_;

    const int r0g = q0 + w * 16 + (lane >> 2);
    const int r1g = r0g + 8;
    const int wmax = q0 + w * 16 + 15;

#define LOADKV4(KT, STG) do {                                                 \
        const int k0_ = (KT) * 64;                                            \
        _Pragma("unroll")                                                     \
        for (int it = 0; it < 16; it++) {                                     \
            int v = it * 256 + tid;                                           \
            int tile = v >> 10;                                               \
            int rr = (v >> 4) & 63;                                           \
            int cc = (v & 15) * 8;                                            \
            const __nv_bfloat16* src =                                        \
                (tile == 0) ? gk_h : (tile == 1) ? gk_l :                     \
                (tile == 2) ? gv_h : gv_l;                                    \
            cpa16(sb + OSTG + (STG) * STGSZ + tile * TILE64B +                \
                      (uint32_t)(rr * KSTR + cc) * 2,                         \
                  src + (size_t)(k0_ + rr) * CKV_ + cc);                      \
        }                                                                     \
        asm volatile("cp.async.commit_group;" ::: "memory");                  \
    } while (0)

    const int lastkt = 2 * qt + 1;
    LOADKV4(0, 0);

    for (int kt = 0; kt <= lastkt; kt++) {
        const int k0 = kt * 64;
        asm volatile("cp.async.wait_group 0;" ::: "memory");
        __syncthreads();
        if (kt < lastkt) LOADKV4(kt + 1, (kt + 1) & 1);

        if (k0 <= wmax) {
            const uint32_t kb = sb + OSTG + (kt & 1) * STGSZ;

            float S[8][4];
#pragma unroll
            for (int j = 0; j < 8; j++)
#pragma unroll
                for (int e = 0; e < 4; e++) S[j][e] = 0.f;

#pragma unroll
            for (int kc2 = 0; kc2 < 4; kc2++) {
#pragma unroll
                for (int j = 0; j < 8; j++) {
                    uint32_t baddr = kb +
                        (((uint32_t)(j * 8 + (lane & 7))) * KSTR +
                         (uint32_t)(kc2 * 32 + (lane >> 3) * 8)) * 2;
                    uint32_t bh[4], bl[4];
                    ldsm4(bh, baddr);
                    ldsm4(bl, baddr + TILE64B);
                    mma_bf(S[j], qh[2 * kc2], bh[0], bh[1]);
                    mma_bf(S[j], qh[2 * kc2], bl[0], bl[1]);
                    mma_bf(S[j], ql[2 * kc2], bh[0], bh[1]);
                    mma_bf(S[j], qh[2 * kc2 + 1], bh[2], bh[3]);
                    mma_bf(S[j], qh[2 * kc2 + 1], bl[2], bl[3]);
                    mma_bf(S[j], ql[2 * kc2 + 1], bh[2], bh[3]);
                }
            }

            uint32_t pah[4][4], pal[4][4];
#pragma unroll
            for (int j = 0; j < 8; j++) {
                int cb = k0 + j * 8 + (lane & 3) * 2;
                float e0 = (cb     <= r0g) ? __expf(S[j][0]) : 0.f;
                float e1 = (cb + 1 <= r0g) ? __expf(S[j][1]) : 0.f;
                float e2 = (cb     <= r1g) ? __expf(S[j][2]) : 0.f;
                float e3 = (cb + 1 <= r1g) ? __expf(S[j][3]) : 0.f;
                l0 += e0 + e1;
                l1 += e2 + e3;
                int kc = j >> 1, hf = (j & 1) * 2;
                pah[kc][hf]     = packsplit(e0, e1, &pal[kc][hf]);
                pah[kc][hf + 1] = packsplit(e2, e3, &pal[kc][hf + 1]);
            }

#pragma unroll
            for (int kc = 0; kc < 4; kc++) {
#pragma unroll
                for (int n16 = 0; n16 < 8; n16++) {
                    uint32_t vaddr = kb + 2 * TILE64B +
                        (((uint32_t)(kc * 16 + (lane & 15))) * KSTR +
                         (uint32_t)(n16 * 16 + (lane >> 4) * 8)) * 2;
                    uint32_t vh[4], vl[4];
                    ldsm4t(vh, vaddr);
                    ldsm4t(vl, vaddr + TILE64B);
                    mma_bf(o[2 * n16],     pah[kc], vh[0], vh[1]);
                    mma_bf(o[2 * n16],     pah[kc], vl[0], vl[1]);
                    mma_bf(o[2 * n16],     pal[kc], vh[0], vh[1]);
                    mma_bf(o[2 * n16 + 1], pah[kc], vh[2], vh[3]);
                    mma_bf(o[2 * n16 + 1], pah[kc], vl[2], vl[3]);
                    mma_bf(o[2 * n16 + 1], pal[kc], vh[2], vh[3]);
                }
            }
        }
    }

    l0 += __shfl_xor_sync(0xffffffffu, l0, 1);
    l0 += __shfl_xor_sync(0xffffffffu, l0, 2);
    l1 += __shfl_xor_sync(0xffffffffu, l1, 1);
    l1 += __shfl_xor_sync(0xffffffffu, l1, 2);
    float i0 = 1.f / l0, i1 = 1.f / l1;

    __nv_bfloat16* yh = g_yhi + ((size_t)(b * T_ + r0g)) * C_ + h * HD_ + (lane & 3) * 2;
    __nv_bfloat16* yl = g_ylo + ((size_t)(b * T_ + r0g)) * C_ + h * HD_ + (lane & 3) * 2;
#pragma unroll
    for (int nt = 0; nt < 16; nt++) {
        int coff = nt * 8;
        uint32_t lo0, lo1;
        uint32_t hi0 = packsplit(o[nt][0] * i0, o[nt][1] * i0, &lo0);
        uint32_t hi1 = packsplit(o[nt][2] * i1, o[nt][3] * i1, &lo1);
        *(uint32_t*)(yh + coff)           = hi0;
        *(uint32_t*)(yl + coff)           = lo0;
        *(uint32_t*)(yh + 8 * C_ + coff)  = hi1;
        *(uint32_t*)(yl + 8 * C_ + coff)  = lo1;
    }
#undef LOADKV4
}

// ---------------------------------------------------------------------------
extern "C" void kernel_launch(void* const* d_in, const int* in_sizes, int n_in,
                              void* d_out, int out_size)
{
    const float* x  = (const float*)d_in[0];
    const float* wq = (const float*)d_in[1];
    const float* wk = (const float*)d_in[2];
    const float* wv = (const float*)d_in[3];
    const float* wo = (const float*)d_in[4];
    const float* sp = (const float*)d_in[5];
    const float* cp = (const float*)d_in[6];
    float* out = (float*)d_out;

    __nv_bfloat16 *xhi, *xlo, *yhi, *ylo, *whi, *wlo, *wohi, *wolo;
    cudaGetSymbolAddress((void**)&xhi, g_xhi);
    cudaGetSymbolAddress((void**)&xlo, g_xlo);
    cudaGetSymbolAddress((void**)&yhi, g_yhi);
    cudaGetSymbolAddress((void**)&ylo, g_ylo);
    cudaGetSymbolAddress((void**)&whi, g_whi);
    cudaGetSymbolAddress((void**)&wlo, g_wlo);
    cudaGetSymbolAddress((void**)&wohi, g_wohi);
    cudaGetSymbolAddress((void**)&wolo, g_wolo);

    cudaFuncSetAttribute(hgemm2, cudaFuncAttributeMaxDynamicSharedMemorySize,
                         G2_SMEM);
    cudaFuncSetAttribute(attn4, cudaFuncAttributeMaxDynamicSharedMemorySize,
                         ATTN4_SMEM);

    // Pre-split inputs/weights to bf16 hi/lo
    int nx = MTOT * C_;
    split_kernel<<<nx / 4 / 256, 256>>>(x, xhi, xlo, nx);
    packw_kernel<<<(C_ * NQKV / 4) / 256, 256>>>(wq, wk, wv, whi, wlo);
    split_kernel<<<(C_ * C_ / 4) / 256, 256>>>(wo, wohi, wolo, C_ * C_);

    // Fused QKV projection + RoPE + bf16 split (all in one kernel's epilogue)
    hgemm2<<<dim3(NQKV / BN, MTOT / BM), 128, G2_SMEM>>>(
        xhi, xlo, whi, wlo, NQKV, C_, nullptr, 1, sp, cp);

    // attn4: 128 q-rows/CTA, cp.async double-buffered KV -> yhi/ylo
    attn4<<<dim3(T_ / 128, H_, B_), 256, ATTN4_SMEM>>>();

    // Output projection (fp32 to harness buffer)
    hgemm2<<<dim3(C_ / BN, MTOT / BM), 128, G2_SMEM>>>(
        yhi, ylo, wohi, wolo, C_, C_, out, 0, nullptr, nullptr);
}